// round 17
// baseline (speedup 1.0000x reference)
#include <cuda_runtime.h>
#include <cuda_bf16.h>

// FM_12060268167845: factorization machine forward.
//   d_in[0] idx  i32 [B,K], d_in[1] x f32 [B,K], d_in[2] b f32 [B,K],
//   d_in[3] w f32 [1M,1], d_in[4] V f32 [1M,128], d_in[5] bias f32 [1]
// out f32 [B] = sigmoid(bias + Xw + 0.5/sum(x) * sum_f((XV)^2 - X2V2))
//
// v16 = v13 (dual per-row sorted streams; traffic at the ~453MB DRAM
// compulsory floor / ~11TB/s LTS) with the A/B batches software-pipelined
// at U=5: preload A(5)+B(5), then alternate consumeA/loadA-next,
// consumeB/loadB-next. One stream's loads are always outstanding while
// the other consumes -> per-warp outstanding never drains to zero, so the
// DRAM-miss stream stays dense even with LTS near its service cap.
// Transient register footprint identical to v13 (40 regs of v buffers).

#define FM_B 8192
#define FM_K 200
#define FM_F 128
#define WARPS 4
#define THREADS (WARPS * 32)
#define U 5                        // FM_K % U == 0 (40 batches per row)
#define NBIN 8
#define BIN_SHIFT 26               // 64MB slices of the 512MB V table
#define CHUNKS 7                   // ceil(200/32)

__device__ __forceinline__ void load_batch(float4 (&v)[U],
                                           const char* __restrict__ Vb,
                                           const unsigned* __restrict__ offp,
                                           int k0, unsigned lane_off)
{
    #pragma unroll
    for (int u = 0; u < U; ++u)
        v[u] = __ldcg((const float4*)(Vb + offp[k0 + u] + lane_off));
}

__device__ __forceinline__ void consume_batch(const float4 (&v)[U],
                                              const float* __restrict__ xp,
                                              int k0, float4& a1, float& a2s)
{
    #pragma unroll
    for (int u = 0; u < U; ++u) {
        float x  = xp[k0 + u];
        float x2 = x * x;
        a1.x = fmaf(x, v[u].x, a1.x);
        a1.y = fmaf(x, v[u].y, a1.y);
        a1.z = fmaf(x, v[u].z, a1.z);
        a1.w = fmaf(x, v[u].w, a1.w);
        float n2 = fmaf(v[u].x, v[u].x,
                   fmaf(v[u].y, v[u].y,
                   fmaf(v[u].z, v[u].z, v[u].w * v[u].w)));
        a2s = fmaf(x2, n2, a2s);
    }
}

__global__ __launch_bounds__(THREADS, 8)
void fm_kernel(const int* __restrict__ idx,
               const float* __restrict__ x_vals,
               const float* __restrict__ b_vals,
               const float* __restrict__ w,
               const float* __restrict__ V,
               const float* __restrict__ bias,
               float* __restrict__ out)
{
    const int warp = threadIdx.x >> 5;
    const int lane = threadIdx.x & 31;
    const unsigned lt_mask = (1u << lane) - 1u;

    __shared__ unsigned s_off[WARPS][2][FM_K];
    __shared__ float    s_x[WARPS][2][FM_K];
    __shared__ float    s_scal[WARPS][4];     // xwA, sxA, xwB, sxB

    const int gwarp = blockIdx.x * WARPS + warp;   // 0..4095
    const int bA    = gwarp * 2;                   // rows bA, bA+1

    // ---- per-row: stage + ballot bin-sort (v13's proven prologue) ----
    for (int r = 0; r < 2; ++r) {
        const int base = (bA + r) * FM_K;

        unsigned eoff[CHUNKS];
        float    ex[CHUNKS];
        float xw = 0.0f, sx = 0.0f;
        #pragma unroll
        for (int c = 0; c < CHUNKS; ++c) {
            int k = c * 32 + lane;
            if (k < FM_K) {
                int   id = idx[base + k];
                float xv = x_vals[base + k];
                eoff[c] = (unsigned)id * (FM_F * 4u);    // id * 512 bytes
                ex[c]   = xv;
                sx += xv;
                xw = fmaf(b_vals[base + k], __ldg(&w[id]), xw);
            } else {
                eoff[c] = 0xFFFFFFFFu;                   // sentinel: no bin
                ex[c]   = 0.0f;
            }
        }

        #pragma unroll
        for (int o = 16; o > 0; o >>= 1) {
            xw += __shfl_down_sync(0xffffffffu, xw, o);
            sx += __shfl_down_sync(0xffffffffu, sx, o);
        }
        if (lane == 0) {
            s_scal[warp][2 * r + 0] = xw;
            s_scal[warp][2 * r + 1] = sx;
        }

        int cnt[NBIN];
        #pragma unroll
        for (int bb = 0; bb < NBIN; ++bb) cnt[bb] = 0;
        #pragma unroll
        for (int c = 0; c < CHUNKS; ++c) {
            unsigned bin = eoff[c] >> BIN_SHIFT;
            #pragma unroll
            for (int bb = 0; bb < NBIN; ++bb)
                cnt[bb] += __popc(__ballot_sync(0xffffffffu, bin == (unsigned)bb));
        }
        int run[NBIN];
        {
            int acc = 0;
            #pragma unroll
            for (int bb = 0; bb < NBIN; ++bb) { run[bb] = acc; acc += cnt[bb]; }
        }
        #pragma unroll
        for (int c = 0; c < CHUNKS; ++c) {
            unsigned bin = eoff[c] >> BIN_SHIFT;
            #pragma unroll
            for (int bb = 0; bb < NBIN; ++bb) {
                unsigned msk = __ballot_sync(0xffffffffu, bin == (unsigned)bb);
                if (bin == (unsigned)bb) {
                    int pos = run[bb] + __popc(msk & lt_mask);
                    s_off[warp][r][pos] = eoff[c];
                    s_x[warp][r][pos]   = ex[c];
                }
                run[bb] += __popc(msk);
            }
        }
    }
    __syncwarp();

    // ---- A/B software-pipelined mainloop: never zero outstanding ----
    const char* __restrict__ Vb = (const char*)V;
    const unsigned lane_off = (unsigned)lane << 4;
    const unsigned* __restrict__ offA = s_off[warp][0];
    const unsigned* __restrict__ offB = s_off[warp][1];
    const float*    __restrict__ xA   = s_x[warp][0];
    const float*    __restrict__ xB   = s_x[warp][1];

    float4 a1A = make_float4(0.f, 0.f, 0.f, 0.f);
    float4 a1B = make_float4(0.f, 0.f, 0.f, 0.f);
    float  a2A = 0.0f, a2B = 0.0f;

    float4 vA[U], vB[U];
    load_batch(vA, Vb, offA, 0, lane_off);
    load_batch(vB, Vb, offB, 0, lane_off);

    for (int k0 = 0; k0 < FM_K - U; k0 += U) {
        consume_batch(vA, xA, k0, a1A, a2A);
        load_batch(vA, Vb, offA, k0 + U, lane_off);
        consume_batch(vB, xB, k0, a1B, a2B);
        load_batch(vB, Vb, offB, k0 + U, lane_off);
    }
    consume_batch(vA, xA, FM_K - U, a1A, a2A);
    consume_batch(vB, xB, FM_K - U, a1B, a2B);

    // ---- reductions + outputs ----
    float pqA = fmaf(a1A.x, a1A.x,
                fmaf(a1A.y, a1A.y,
                fmaf(a1A.z, a1A.z, a1A.w * a1A.w))) - a2A;
    float pqB = fmaf(a1B.x, a1B.x,
                fmaf(a1B.y, a1B.y,
                fmaf(a1B.z, a1B.z, a1B.w * a1B.w))) - a2B;

    #pragma unroll
    for (int o = 16; o > 0; o >>= 1) {
        pqA += __shfl_down_sync(0xffffffffu, pqA, o);
        pqB += __shfl_down_sync(0xffffffffu, pqB, o);
    }

    if (lane == 0) {
        float bia = bias[0];
        float pA  = 0.5f * (1.0f / s_scal[warp][1]) * pqA;
        out[bA]     = 1.0f / (1.0f + __expf(-(bia + s_scal[warp][0] + pA)));
        float pB  = 0.5f * (1.0f / s_scal[warp][3]) * pqB;
        out[bA + 1] = 1.0f / (1.0f + __expf(-(bia + s_scal[warp][2] + pB)));
    }
}

extern "C" void kernel_launch(void* const* d_in, const int* in_sizes, int n_in,
                              void* d_out, int out_size)
{
    const int*   idx    = (const int*)d_in[0];
    const float* x_vals = (const float*)d_in[1];
    const float* b_vals = (const float*)d_in[2];
    const float* w      = (const float*)d_in[3];
    const float* V      = (const float*)d_in[4];
    const float* bias   = (const float*)d_in[5];
    float*       out    = (float*)d_out;
    (void)in_sizes; (void)n_in; (void)out_size;

    const int grid = FM_B / (WARPS * 2);   // 1024 CTAs: one resident wave
    fm_kernel<<<grid, THREADS>>>(idx, x_vals, b_vals, w, V, bias, out);
}